// round 14
// baseline (speedup 1.0000x reference)
#include <cuda_runtime.h>

#define BATCH 8
#define NPTS  4096
#define KNN   16
#define GRIDW 96
#define CELLS (BATCH * GRIDW * GRIDW)
#define MAXP  32
#define HID   128
#define OUTC  64
#define WPB   16  // warps per MLP block
#define PP    4   // points per warp (2 f32x2 pairs)

typedef unsigned long long ull;

// Scratch
__device__ int    g_cnt[CELLS];
__device__ float4 g_cell[CELLS * MAXP];              // (x, y, idx_as_float, unused)
__device__ float  g_emb[BATCH * NPTS * 2 * KNN];     // point-major; only first 2*cnt written (rest stay 0)
__device__ int    g_pcnt[BATCH * NPTS];              // neighbor count per point

// ---------- f32x2 helpers ----------
__device__ __forceinline__ void fma2(ull &d, ull a, ull b) {
    asm("fma.rn.f32x2 %0, %1, %2, %0;" : "+l"(d) : "l"(a), "l"(b));
}
__device__ __forceinline__ ull dup2(float x) {
    ull r; unsigned u = __float_as_uint(x);
    asm("mov.b64 %0, {%1, %1};" : "=l"(r) : "r"(u));
    return r;
}
__device__ __forceinline__ ull pack2(float a, float b) {
    ull r; unsigned ua = __float_as_uint(a), ub = __float_as_uint(b);
    asm("mov.b64 %0, {%1, %2};" : "=l"(r) : "r"(ua), "r"(ub));
    return r;
}
__device__ __forceinline__ float2 unp2(ull v) {
    unsigned a, b;
    asm("mov.b64 {%0, %1}, %2;" : "=r"(a), "=r"(b) : "l"(v));
    return make_float2(__uint_as_float(a), __uint_as_float(b));
}

__global__ void k_zero() {
    int i = blockIdx.x * blockDim.x + threadIdx.x;
    if (i < CELLS) g_cnt[i] = 0;
}

__global__ void k_build(const float4* __restrict__ xytp4) {
    int i = blockIdx.x * blockDim.x + threadIdx.x;
    if (i >= BATCH * NPTS) return;
    float4 v = xytp4[i];
    float x = v.y, y = v.z;
    int cx = min(GRIDW - 1, max(0, (int)(x * (float)GRIDW)));
    int cy = min(GRIDW - 1, max(0, (int)(y * (float)GRIDW)));
    int b = i >> 12;
    int cell = b * GRIDW * GRIDW + cy * GRIDW + cx;
    int p = atomicAdd(&g_cnt[cell], 1);
    if (p < MAXP) g_cell[cell * MAXP + p] = make_float4(x, y, __int_as_float(i & (NPTS - 1)), 0.f);
}

// Thread-per-point ball query; writes only the nonzero prefix of the embedding
// (slots >= 2*cnt are exact zeros in the reference; g_emb stays 0 there).
__global__ void k_query(const float4* __restrict__ xytp4) {
    int i = blockIdx.x * blockDim.x + threadIdx.x;
    if (i >= BATCH * NPTS) return;
    int b = i >> 12;
    int n = i & (NPTS - 1);
    const float4* base4 = xytp4 + (size_t)b * NPTS;
    float4 q = base4[n];
    float xq = q.y, yq = q.z;
    float sqn = __fadd_rn(__fmul_rn(xq, xq), __fmul_rn(yq, yq));
    const float R2 = (float)((5.0 / 480.0) * (5.0 / 480.0));

    int cx = min(GRIDW - 1, max(0, (int)(xq * (float)GRIDW)));
    int cy = min(GRIDW - 1, max(0, (int)(yq * (float)GRIDW)));
    int y0 = max(cy - 1, 0), y1 = min(cy + 1, GRIDW - 1);
    int x0 = max(cx - 1, 0), x1 = min(cx + 1, GRIDW - 1);

    int best[KNN];
    int cnt = 0;

    for (int gy = y0; gy <= y1; gy++) {
        for (int gx = x0; gx <= x1; gx++) {
            int cell = b * GRIDW * GRIDW + gy * GRIDW + gx;
            int c = min(g_cnt[cell], MAXP);
            const float4* cp = g_cell + cell * MAXP;
            for (int j = 0; j < c; j++) {
                float4 pc = cp[j];
                float xm = pc.x, ym = pc.y;
                int   m  = __float_as_int(pc.z);
                float sqm = __fadd_rn(__fmul_rn(xm, xm), __fmul_rn(ym, ym));
                float dot = __fmaf_rn(yq, ym, __fmul_rn(xq, xm));
                float d2  = __fsub_rn(__fadd_rn(sqn, sqm), __fmul_rn(2.0f, dot));
                if (d2 < R2) {
                    if (cnt < KNN) {
                        int t = cnt++;
                        while (t > 0 && best[t - 1] > m) { best[t] = best[t - 1]; t--; }
                        best[t] = m;
                    } else if (m < best[KNN - 1]) {
                        int t = KNN - 1;
                        while (t > 0 && best[t - 1] > m) { best[t] = best[t - 1]; t--; }
                        best[t] = m;
                    }
                }
            }
        }
    }

    g_pcnt[i] = cnt;
    float* e = g_emb + (size_t)i * (2 * KNN);
    for (int k = 0; k < cnt; k++) {
        float4 t = base4[best[k]];
        e[2 * k]     = __fsub_rn(xq, t.y);
        e[2 * k + 1] = __fsub_rn(yq, t.z);
    }
}

// MLP: f32x2 point-pair packing + sparse layer 1 (W1 rows read via L1/__ldg).
// smem: sW2 + biases + sE + sH = 74.5 KB -> 3 CTAs/SM; launch_bounds(512,3).
extern __shared__ float smem[];
__global__ void __launch_bounds__(WPB * 32, 3) k_mlp(
        const float* __restrict__ W1, const float* __restrict__ b1,
        const float* __restrict__ W2, const float* __restrict__ b2,
        float* __restrict__ out) {
    float* sW2 = smem;                    // 8192
    float* sb1 = sW2 + HID * OUTC;        // 128
    float* sb2 = sb1 + HID;               // 64
    float* sE  = sb2 + OUTC;              // WPB*PP*32 = 2048 (pair-interleaved)
    float* sH  = sE + WPB * PP * 32;      // WPB*PP*HID = 8192 (pair-interleaved)

    int tid  = threadIdx.x;
    int warp = tid >> 5;
    int lane = tid & 31;
    int pbase = blockIdx.x * (WPB * PP);  // block covers 64 points

    for (int j = tid; j < HID * OUTC; j += blockDim.x) sW2[j] = W2[j];
    if (tid < HID)  sb1[tid] = b1[tid];
    if (tid < OUTC) sb2[tid] = b2[tid];
    // Stage embeddings pair-interleaved: sE[w*128 + (pr*32+e)*2 + ab]
    for (int j = tid; j < WPB * PP * 32; j += blockDim.x) {
        int lp = j >> 5;              // local point
        int e  = j & 31;
        int w  = lp >> 2;
        int pr = (lp & 3) >> 1;
        int ab = lp & 1;
        sE[w * 128 + (pr * 32 + e) * 2 + ab] = g_emb[(size_t)(pbase + lp) * 32 + e];
    }
    __syncthreads();

    const float* eb = sE + warp * 128;
    float* hb = sH + warp * (PP * HID);
    int p0 = pbase + warp * PP;

    // per-pair loop bounds (uniform across the warp)
    int bound0 = 2 * max(g_pcnt[p0],     g_pcnt[p0 + 1]);
    int bound1 = 2 * max(g_pcnt[p0 + 2], g_pcnt[p0 + 3]);

    // ---- Layer 1 (sparse): lane owns hidden cols 4l..4l+3; W1 from L1 ----
    ull acc[2][4];
    {
        float4 bv = *(const float4*)&sb1[4 * lane];
        ull b0 = dup2(bv.x), b1v = dup2(bv.y), b2v = dup2(bv.z), b3v = dup2(bv.w);
        #pragma unroll
        for (int pr = 0; pr < 2; pr++) {
            acc[pr][0] = b0; acc[pr][1] = b1v; acc[pr][2] = b2v; acc[pr][3] = b3v;
        }
    }
    #pragma unroll
    for (int pr = 0; pr < 2; pr++) {
        int bound = pr == 0 ? bound0 : bound1;
        for (int e = 0; e < bound; e++) {
            float4 w = __ldg((const float4*)&W1[e * HID + 4 * lane]);
            ull v = *(const ull*)&eb[(pr * 32 + e) * 2];   // (embA, embB) broadcast
            fma2(acc[pr][0], v, dup2(w.x));
            fma2(acc[pr][1], v, dup2(w.y));
            fma2(acc[pr][2], v, dup2(w.z));
            fma2(acc[pr][3], v, dup2(w.w));
        }
    }
    #pragma unroll
    for (int pr = 0; pr < 2; pr++) {
        #pragma unroll
        for (int c = 0; c < 4; c++) {
            float2 f = unp2(acc[pr][c]);
            f.x = fmaxf(f.x, 0.0f);
            f.y = fmaxf(f.y, 0.0f);
            acc[pr][c] = pack2(f.x, f.y);
        }
        *(ulonglong2*)&hb[pr * 256 + 8 * lane]     = make_ulonglong2(acc[pr][0], acc[pr][1]);
        *(ulonglong2*)&hb[pr * 256 + 8 * lane + 4] = make_ulonglong2(acc[pr][2], acc[pr][3]);
    }
    __syncwarp();

    // ---- Layer 2 (dense): lane owns output cols 2l, 2l+1 ----
    ull ox[2], oy[2];
    {
        float2 bv = *(const float2*)&sb2[2 * lane];
        ull bx = dup2(bv.x), by = dup2(bv.y);
        #pragma unroll
        for (int pr = 0; pr < 2; pr++) { ox[pr] = bx; oy[pr] = by; }
    }
    #pragma unroll 8
    for (int h2 = 0; h2 < HID / 2; h2++) {
        float2 wa = *(const float2*)&sW2[(2 * h2 + 0) * OUTC + 2 * lane];
        float2 wb = *(const float2*)&sW2[(2 * h2 + 1) * OUTC + 2 * lane];
        ull wax = dup2(wa.x), way = dup2(wa.y);
        ull wbx = dup2(wb.x), wby = dup2(wb.y);
        #pragma unroll
        for (int pr = 0; pr < 2; pr++) {
            ulonglong2 hv = *(const ulonglong2*)&hb[pr * 256 + 4 * h2];
            fma2(ox[pr], hv.x, wax);
            fma2(oy[pr], hv.x, way);
            fma2(ox[pr], hv.y, wbx);
            fma2(oy[pr], hv.y, wby);
        }
    }
    #pragma unroll
    for (int pr = 0; pr < 2; pr++) {
        int pA = p0 + 2 * pr;
        float2 fx = unp2(ox[pr]);
        float2 fy = unp2(oy[pr]);
        *(float2*)&out[(size_t)pA * OUTC + 2 * lane]       = make_float2(fx.x, fy.x);
        *(float2*)&out[(size_t)(pA + 1) * OUTC + 2 * lane] = make_float2(fx.y, fy.y);
    }
}

extern "C" void kernel_launch(void* const* d_in, const int* in_sizes, int n_in,
                              void* d_out, int out_size) {
    const float4* xytp4 = (const float4*)d_in[0];
    const float* W1 = (const float*)d_in[1];
    const float* b1 = (const float*)d_in[2];
    const float* W2 = (const float*)d_in[3];
    const float* b2 = (const float*)d_in[4];
    float* out = (float*)d_out;

    k_zero<<<(CELLS + 255) / 256, 256>>>();
    k_build<<<(BATCH * NPTS + 255) / 256, 256>>>(xytp4);
    k_query<<<(BATCH * NPTS + 127) / 128, 128>>>(xytp4);

    const int smem_floats = HID * OUTC + HID + OUTC + WPB * PP * 32 + WPB * PP * HID;
    const int smem_bytes = smem_floats * (int)sizeof(float);   // 74.5 KB
    cudaFuncSetAttribute(k_mlp, cudaFuncAttributeMaxDynamicSharedMemorySize, smem_bytes);
    int nblocks = (BATCH * NPTS) / (WPB * PP);   // 512
    k_mlp<<<nblocks, WPB * 32, smem_bytes>>>(W1, b1, W2, b2, out);
}

// round 17
// speedup vs baseline: 1.1553x; 1.1553x over previous
#include <cuda_runtime.h>

#define BATCH 8
#define NPTS  4096
#define KNN   16
#define GRIDW 96
#define CELLS (BATCH * GRIDW * GRIDW)
#define MAXP  32
#define HID   128
#define OUTC  64
#define WPB   16  // warps per MLP block
#define PP    4   // points per warp (2 f32x2 pairs)

typedef unsigned long long ull;

// Scratch
__device__ int    g_cnt[CELLS];                      // zeroed by k_mlp tail each run
__device__ float4 g_cell[CELLS * MAXP];              // (x, y, idx_as_float, unused)
__device__ float  g_emb[BATCH * NPTS * 2 * KNN];     // only first 2*cnt written (rest stay 0)
__device__ int    g_pcnt[BATCH * NPTS];              // neighbor count per point

// ---------- f32x2 helpers ----------
__device__ __forceinline__ void fma2(ull &d, ull a, ull b) {
    asm("fma.rn.f32x2 %0, %1, %2, %0;" : "+l"(d) : "l"(a), "l"(b));
}
__device__ __forceinline__ ull dup2(float x) {
    ull r; unsigned u = __float_as_uint(x);
    asm("mov.b64 %0, {%1, %1};" : "=l"(r) : "r"(u));
    return r;
}
__device__ __forceinline__ ull pack2(float a, float b) {
    ull r; unsigned ua = __float_as_uint(a), ub = __float_as_uint(b);
    asm("mov.b64 %0, {%1, %2};" : "=l"(r) : "r"(ua), "r"(ub));
    return r;
}
__device__ __forceinline__ float2 unp2(ull v) {
    unsigned a, b;
    asm("mov.b64 {%0, %1}, %2;" : "=r"(a), "=r"(b) : "l"(v));
    return make_float2(__uint_as_float(a), __uint_as_float(b));
}

__global__ void k_build(const float4* __restrict__ xytp4) {
    int i = blockIdx.x * blockDim.x + threadIdx.x;
    if (i >= BATCH * NPTS) return;
    float4 v = xytp4[i];
    float x = v.y, y = v.z;
    int cx = min(GRIDW - 1, max(0, (int)(x * (float)GRIDW)));
    int cy = min(GRIDW - 1, max(0, (int)(y * (float)GRIDW)));
    int b = i >> 12;
    int cell = b * GRIDW * GRIDW + cy * GRIDW + cx;
    int p = atomicAdd(&g_cnt[cell], 1);
    if (p < MAXP) g_cell[cell * MAXP + p] = make_float4(x, y, __int_as_float(i & (NPTS - 1)), 0.f);
}

// Quarter-warp (4 threads/point) ball query. Lanes split the 3x3 cells, each
// keeps its own sorted-ascending candidate-index list (identical per-candidate
// float arithmetic as the reference replica), then a width-4 shuffle merge
// emits the global smallest-16 in index order. Writes only the nonzero prefix.
__global__ void __launch_bounds__(128) k_query(const float4* __restrict__ xytp4) {
    const unsigned FULL = 0xffffffffu;
    int t = blockIdx.x * blockDim.x + threadIdx.x;
    int i = t >> 2;                       // point index
    int sub = t & 3;                      // 0..3 within quarter
    if (i >= BATCH * NPTS) return;
    int b = i >> 12;
    int n = i & (NPTS - 1);
    const float4* base4 = xytp4 + (size_t)b * NPTS;
    float4 q = base4[n];
    float xq = q.y, yq = q.z;
    float sqn = __fadd_rn(__fmul_rn(xq, xq), __fmul_rn(yq, yq));
    const float R2 = (float)((5.0 / 480.0) * (5.0 / 480.0));

    int cx = min(GRIDW - 1, max(0, (int)(xq * (float)GRIDW)));
    int cy = min(GRIDW - 1, max(0, (int)(yq * (float)GRIDW)));
    int y0 = max(cy - 1, 0), y1 = min(cy + 1, GRIDW - 1);
    int x0 = max(cx - 1, 0), x1 = min(cx + 1, GRIDW - 1);
    int nx = x1 - x0 + 1;
    int ncell = (y1 - y0 + 1) * nx;

    int best[KNN];
    int cnt = 0;

    // this lane's cells: sub, sub+4, sub+8
    for (int c = sub; c < ncell; c += 4) {
        int gy = y0 + c / nx;
        int gx = x0 + c % nx;
        int cell = b * GRIDW * GRIDW + gy * GRIDW + gx;
        int cc = min(g_cnt[cell], MAXP);
        const float4* cp = g_cell + cell * MAXP;
        for (int j = 0; j < cc; j++) {
            float4 pc = cp[j];
            float xm = pc.x, ym = pc.y;
            int   m  = __float_as_int(pc.z);
            float sqm = __fadd_rn(__fmul_rn(xm, xm), __fmul_rn(ym, ym));
            float dot = __fmaf_rn(yq, ym, __fmul_rn(xq, xm));
            float d2  = __fsub_rn(__fadd_rn(sqn, sqm), __fmul_rn(2.0f, dot));
            if (d2 < R2) {
                if (cnt < KNN) {
                    int s = cnt++;
                    while (s > 0 && best[s - 1] > m) { best[s] = best[s - 1]; s--; }
                    best[s] = m;
                } else if (m < best[KNN - 1]) {
                    int s = KNN - 1;
                    while (s > 0 && best[s - 1] > m) { best[s] = best[s - 1]; s--; }
                    best[s] = m;
                }
            }
        }
    }

    // width-4 merge of the four sorted lists; slot k handled by lane (k&3)
    float* e = g_emb + (size_t)i * (2 * KNN);
    int pos = 0;
    int k;
    for (k = 0; k < KNN; k++) {
        int head = (pos < cnt) ? best[pos] : 0x7fffffff;
        int mn = head;
        mn = min(mn, __shfl_xor_sync(FULL, mn, 1, 4));
        mn = min(mn, __shfl_xor_sync(FULL, mn, 2, 4));
        if (mn == 0x7fffffff) break;
        if (head == mn) pos++;           // advance winner (ties impossible: unique indices)
        if (sub == (k & 3)) {
            float4 tt = base4[mn];
            e[2 * k]     = __fsub_rn(xq, tt.y);
            e[2 * k + 1] = __fsub_rn(yq, tt.z);
        }
    }
    if (sub == 0) g_pcnt[i] = k;
}

// MLP: unchanged from R14 (f32x2 pairs, sparse layer 1, W1 via __ldg),
// plus: zeroes g_cnt for the next replay (runs after k_query).
extern __shared__ float smem[];
__global__ void __launch_bounds__(WPB * 32, 3) k_mlp(
        const float* __restrict__ W1, const float* __restrict__ b1,
        const float* __restrict__ W2, const float* __restrict__ b2,
        float* __restrict__ out) {
    float* sW2 = smem;                    // 8192
    float* sb1 = sW2 + HID * OUTC;        // 128
    float* sb2 = sb1 + HID;               // 64
    float* sE  = sb2 + OUTC;              // 2048 (pair-interleaved)
    float* sH  = sE + WPB * PP * 32;      // 8192 (pair-interleaved)

    int tid  = threadIdx.x;
    int warp = tid >> 5;
    int lane = tid & 31;
    int pbase = blockIdx.x * (WPB * PP);  // block covers 64 points

    // zero g_cnt for next replay (g_cnt unused by this kernel)
    int gt = blockIdx.x * blockDim.x + tid;
    if (gt < CELLS) g_cnt[gt] = 0;

    for (int j = tid; j < HID * OUTC; j += blockDim.x) sW2[j] = W2[j];
    if (tid < HID)  sb1[tid] = b1[tid];
    if (tid < OUTC) sb2[tid] = b2[tid];
    for (int j = tid; j < WPB * PP * 32; j += blockDim.x) {
        int lp = j >> 5;
        int e  = j & 31;
        int w  = lp >> 2;
        int pr = (lp & 3) >> 1;
        int ab = lp & 1;
        sE[w * 128 + (pr * 32 + e) * 2 + ab] = g_emb[(size_t)(pbase + lp) * 32 + e];
    }
    __syncthreads();

    const float* eb = sE + warp * 128;
    float* hb = sH + warp * (PP * HID);
    int p0 = pbase + warp * PP;

    int bound0 = 2 * max(g_pcnt[p0],     g_pcnt[p0 + 1]);
    int bound1 = 2 * max(g_pcnt[p0 + 2], g_pcnt[p0 + 3]);

    // ---- Layer 1 (sparse) ----
    ull acc[2][4];
    {
        float4 bv = *(const float4*)&sb1[4 * lane];
        ull b0 = dup2(bv.x), b1v = dup2(bv.y), b2v = dup2(bv.z), b3v = dup2(bv.w);
        #pragma unroll
        for (int pr = 0; pr < 2; pr++) {
            acc[pr][0] = b0; acc[pr][1] = b1v; acc[pr][2] = b2v; acc[pr][3] = b3v;
        }
    }
    #pragma unroll
    for (int pr = 0; pr < 2; pr++) {
        int bound = pr == 0 ? bound0 : bound1;
        for (int e = 0; e < bound; e++) {
            float4 w = __ldg((const float4*)&W1[e * HID + 4 * lane]);
            ull v = *(const ull*)&eb[(pr * 32 + e) * 2];
            fma2(acc[pr][0], v, dup2(w.x));
            fma2(acc[pr][1], v, dup2(w.y));
            fma2(acc[pr][2], v, dup2(w.z));
            fma2(acc[pr][3], v, dup2(w.w));
        }
    }
    #pragma unroll
    for (int pr = 0; pr < 2; pr++) {
        #pragma unroll
        for (int c = 0; c < 4; c++) {
            float2 f = unp2(acc[pr][c]);
            f.x = fmaxf(f.x, 0.0f);
            f.y = fmaxf(f.y, 0.0f);
            acc[pr][c] = pack2(f.x, f.y);
        }
        *(ulonglong2*)&hb[pr * 256 + 8 * lane]     = make_ulonglong2(acc[pr][0], acc[pr][1]);
        *(ulonglong2*)&hb[pr * 256 + 8 * lane + 4] = make_ulonglong2(acc[pr][2], acc[pr][3]);
    }
    __syncwarp();

    // ---- Layer 2 (dense) ----
    ull ox[2], oy[2];
    {
        float2 bv = *(const float2*)&sb2[2 * lane];
        ull bx = dup2(bv.x), by = dup2(bv.y);
        #pragma unroll
        for (int pr = 0; pr < 2; pr++) { ox[pr] = bx; oy[pr] = by; }
    }
    #pragma unroll 8
    for (int h2 = 0; h2 < HID / 2; h2++) {
        float2 wa = *(const float2*)&sW2[(2 * h2 + 0) * OUTC + 2 * lane];
        float2 wb = *(const float2*)&sW2[(2 * h2 + 1) * OUTC + 2 * lane];
        ull wax = dup2(wa.x), way = dup2(wa.y);
        ull wbx = dup2(wb.x), wby = dup2(wb.y);
        #pragma unroll
        for (int pr = 0; pr < 2; pr++) {
            ulonglong2 hv = *(const ulonglong2*)&hb[pr * 256 + 4 * h2];
            fma2(ox[pr], hv.x, wax);
            fma2(oy[pr], hv.x, way);
            fma2(ox[pr], hv.y, wbx);
            fma2(oy[pr], hv.y, wby);
        }
    }
    #pragma unroll
    for (int pr = 0; pr < 2; pr++) {
        int pA = p0 + 2 * pr;
        float2 fx = unp2(ox[pr]);
        float2 fy = unp2(oy[pr]);
        *(float2*)&out[(size_t)pA * OUTC + 2 * lane]       = make_float2(fx.x, fy.x);
        *(float2*)&out[(size_t)(pA + 1) * OUTC + 2 * lane] = make_float2(fx.y, fy.y);
    }
}

extern "C" void kernel_launch(void* const* d_in, const int* in_sizes, int n_in,
                              void* d_out, int out_size) {
    const float4* xytp4 = (const float4*)d_in[0];
    const float* W1 = (const float*)d_in[1];
    const float* b1 = (const float*)d_in[2];
    const float* W2 = (const float*)d_in[3];
    const float* b2 = (const float*)d_in[4];
    float* out = (float*)d_out;

    k_build<<<(BATCH * NPTS + 255) / 256, 256>>>(xytp4);
    k_query<<<(BATCH * NPTS * 4 + 127) / 128, 128>>>(xytp4);   // 4 threads/point

    const int smem_floats = HID * OUTC + HID + OUTC + WPB * PP * 32 + WPB * PP * HID;
    const int smem_bytes = smem_floats * (int)sizeof(float);   // 74.5 KB
    cudaFuncSetAttribute(k_mlp, cudaFuncAttributeMaxDynamicSharedMemorySize, smem_bytes);
    int nblocks = (BATCH * NPTS) / (WPB * PP);   // 512
    k_mlp<<<nblocks, WPB * 32, smem_bytes>>>(W1, b1, W2, b2, out);
}